// round 8
// baseline (speedup 1.0000x reference)
#include <cuda_runtime.h>
#include <cuda_bf16.h>
#include <cstdint>
#include <cstddef>

#define VOCAB   50257
#define VPAD    50304
#define HID     768
#define NGATE   3072
#define KZ      1536
#define MAXLEN  32
#define NB      64
#define VTILES  393
#define GPARTS  6
#define GK      256
#define GTILES  24

#define NSTAGE      3
#define STAGE_BYTES 24576
#define SA_HI 0
#define SA_LO 8192
#define SB_HI 16384
#define SB_LO 20480
#define SMEM_BYTES  73728
#define OFF_SWV 40960
#define OFF_SWI 41984
#define NEG_BIG (-3.402823466e38f)

// ---- device scratch (static; no allocs allowed) ----
__device__ __align__(256) __nv_bfloat16 g_Wouthi[(size_t)VPAD * HID];
__device__ __align__(256) __nv_bfloat16 g_Woutlo[(size_t)VPAD * HID];
__device__ __align__(256) __nv_bfloat16 g_Wghi[NGATE * KZ];
__device__ __align__(256) __nv_bfloat16 g_Wglo[NGATE * KZ];
__device__ __align__(256) float g_h[NB * HID];
__device__ __align__(256) float g_c[NB * HID];
__device__ __align__(256) __nv_bfloat16 g_hhi[NB * HID];
__device__ __align__(256) __nv_bfloat16 g_hlo[NB * HID];
__device__ __align__(256) __nv_bfloat16 g_zhi[NB * KZ];
__device__ __align__(256) __nv_bfloat16 g_zlo[NB * KZ];
__device__ __align__(256) float g_gatesP[GPARTS * NGATE * NB];
__device__ __align__(256) float g_pmax[VTILES * NB];
__device__ __align__(256) int   g_pidx[VTILES * NB];

// ---- helpers ----
__device__ __forceinline__ uint32_t smem_u32(const void* p) {
    uint32_t a;
    asm("{ .reg .u64 t; cvta.to.shared.u64 t, %1; cvt.u32.u64 %0, t; }" : "=r"(a) : "l"(p));
    return a;
}
// SW64: 64B rows, 8-row atom; conflict-free for ldmatrix
#define SWZ64(x) ((uint32_t)(x) ^ ((((uint32_t)(x)) >> 3) & 0x30u))

__device__ __forceinline__ void cpasync16(uint32_t sa, const void* g) {
    asm volatile("cp.async.cg.shared.global [%0], [%1], 16;" :: "r"(sa), "l"(g));
}
__device__ __forceinline__ void cp_commit() { asm volatile("cp.async.commit_group;" ::: "memory"); }
__device__ __forceinline__ void cp_wait1()  { asm volatile("cp.async.wait_group 1;" ::: "memory"); }

__device__ __forceinline__ void ldsm4(uint32_t* r, uint32_t addr) {
    asm volatile("ldmatrix.sync.aligned.m8n8.x4.shared.b16 {%0,%1,%2,%3}, [%4];"
        : "=r"(r[0]), "=r"(r[1]), "=r"(r[2]), "=r"(r[3]) : "r"(addr));
}
__device__ __forceinline__ void mma16816(float* c, const uint32_t* a, const uint32_t* b) {
    asm volatile("mma.sync.aligned.m16n8k16.row.col.f32.bf16.bf16.f32 "
        "{%0,%1,%2,%3}, {%4,%5,%6,%7}, {%8,%9}, {%0,%1,%2,%3};"
        : "+f"(c[0]), "+f"(c[1]), "+f"(c[2]), "+f"(c[3])
        : "r"(a[0]), "r"(a[1]), "r"(a[2]), "r"(a[3]), "r"(b[0]), "r"(b[1]));
}

extern __shared__ __align__(1024) char dyn_smem[];

// load one K=32 chunk (A: 128x32 hi+lo, B: 64x32 hi+lo) into stage
__device__ __forceinline__ void load_chunk(uint32_t sb, int stage,
    const __nv_bfloat16* __restrict__ Ahi, const __nv_bfloat16* __restrict__ Alo,
    long lda, long rowA0,
    const __nv_bfloat16* __restrict__ Bhi, const __nv_bfloat16* __restrict__ Blo,
    long ldb, long kc, int tid)
{
    uint32_t st = sb + (uint32_t)stage * STAGE_BYTES;
#pragma unroll
    for (int i = 0; i < 4; i++) {           // A: 128 rows x 4 x 16B
        int u = tid + i * 128;
        int r = u >> 2, c4 = u & 3;
        size_t g = (size_t)(rowA0 + r) * lda + kc + c4 * 8;
        uint32_t so = SWZ64(r * 64 + c4 * 16);
        cpasync16(st + SA_HI + so, Ahi + g);
        cpasync16(st + SA_LO + so, Alo + g);
    }
#pragma unroll
    for (int i = 0; i < 2; i++) {           // B: 64 rows x 4 x 16B
        int u = tid + i * 128;
        int r = u >> 2, c4 = u & 3;
        size_t g = (size_t)r * ldb + kc + c4 * 8;
        uint32_t so = SWZ64(r * 64 + c4 * 16);
        cpasync16(st + SB_HI + so, Bhi + g);
        cpasync16(st + SB_LO + so, Blo + g);
    }
}

// C[128,64] = sum_K (Ahi+Alo)[128,K] x (Bhi+Blo)[64,K]^T  (3 split GEMMs, lo*lo dropped)
// Result left in smem as float C[m][b], row stride 65 floats (offset 0).
__device__ __forceinline__ void mma_mainloop(
    char* smem, uint32_t sb,
    const __nv_bfloat16* __restrict__ Ahi, const __nv_bfloat16* __restrict__ Alo,
    long lda, long rowA0,
    const __nv_bfloat16* __restrict__ Bhi, const __nv_bfloat16* __restrict__ Blo,
    long ldb, int nchunks)
{
    const int tid = threadIdx.x;
    const int w = tid >> 5, lane = tid & 31;
    float acc[2][8][4];
#pragma unroll
    for (int mt = 0; mt < 2; mt++)
#pragma unroll
        for (int nt = 0; nt < 8; nt++)
#pragma unroll
            for (int r = 0; r < 4; r++) acc[mt][nt][r] = 0.f;

    const int a_r = lane & 15;
    const int a_c = (lane >> 4) << 4;
    const int b_r = (lane & 7) + ((lane & 16) >> 1);
    const int b_c = (lane & 8) << 1;

    load_chunk(sb, 0, Ahi, Alo, lda, rowA0, Bhi, Blo, ldb, 0, tid);
    cp_commit();
    load_chunk(sb, 1, Ahi, Alo, lda, rowA0, Bhi, Blo, ldb, 32, tid);
    cp_commit();

    for (int ch = 0; ch < nchunks; ch++) {
        cp_wait1();
        __syncthreads();
        // Issue loads for ch+2 IMMEDIATELY (target stage (ch+2)%3 == (ch-1)%3,
        // drained by the barrier above). Two chunks now in flight during compute.
        if (ch + 2 < nchunks)
            load_chunk(sb, (ch + 2) % NSTAGE, Ahi, Alo, lda, rowA0,
                       Bhi, Blo, ldb, (long)(ch + 2) * 32, tid);
        cp_commit();

        uint32_t st = sb + (uint32_t)(ch % NSTAGE) * STAGE_BYTES;
#pragma unroll
        for (int ks = 0; ks < 2; ks++) {
            const int kb = ks * 32;
            uint32_t ah[2][4], al[2][4];
#pragma unroll
            for (int mt = 0; mt < 2; mt++) {
                uint32_t so = SWZ64((w * 32 + mt * 16 + a_r) * 64 + kb + a_c);
                ldsm4(ah[mt], st + SA_HI + so);
                ldsm4(al[mt], st + SA_LO + so);
            }
            uint32_t bh[4][4], bl[4][4];
#pragma unroll
            for (int p = 0; p < 4; p++) {
                uint32_t so = SWZ64((p * 16 + b_r) * 64 + kb + b_c);
                ldsm4(bh[p], st + SB_HI + so);
                ldsm4(bl[p], st + SB_LO + so);
            }
            // term-major: 16 independent MMAs between touches of the same acc regs
#pragma unroll
            for (int mt = 0; mt < 2; mt++)
#pragma unroll
                for (int p = 0; p < 4; p++) {
                    mma16816(acc[mt][2 * p],     ah[mt], &bh[p][0]);
                    mma16816(acc[mt][2 * p + 1], ah[mt], &bh[p][2]);
                }
#pragma unroll
            for (int mt = 0; mt < 2; mt++)
#pragma unroll
                for (int p = 0; p < 4; p++) {
                    mma16816(acc[mt][2 * p],     ah[mt], &bl[p][0]);
                    mma16816(acc[mt][2 * p + 1], ah[mt], &bl[p][2]);
                }
#pragma unroll
            for (int mt = 0; mt < 2; mt++)
#pragma unroll
                for (int p = 0; p < 4; p++) {
                    mma16816(acc[mt][2 * p],     al[mt], &bh[p][0]);
                    mma16816(acc[mt][2 * p + 1], al[mt], &bh[p][2]);
                }
        }
    }
    __syncthreads();
    float* C = (float*)smem;
#pragma unroll
    for (int mt = 0; mt < 2; mt++)
#pragma unroll
        for (int nt = 0; nt < 8; nt++)
#pragma unroll
            for (int r = 0; r < 4; r++) {
                int m = w * 32 + mt * 16 + (lane >> 2) + ((r & 2) ? 8 : 0);
                int n = nt * 8 + 2 * (lane & 3) + (r & 1);
                C[m * 65 + n] = acc[mt][nt][r];
            }
    __syncthreads();
}

// ---- prep kernels ----
__global__ void k_split_wout(const float* __restrict__ W) {
    size_t i = (size_t)blockIdx.x * 256 + threadIdx.x;
    if (i >= (size_t)VPAD * HID) return;
    float w = (i < (size_t)VOCAB * HID) ? W[i] : 0.f;
    __nv_bfloat16 hi = __float2bfloat16(w);
    g_Wouthi[i] = hi;
    g_Woutlo[i] = __float2bfloat16(w - __bfloat162float(hi));
}
__global__ void k_split_wg(const float* __restrict__ Wih, const float* __restrict__ Whh) {
    int i = blockIdx.x * 256 + threadIdx.x;
    if (i >= NGATE * KZ) return;
    int j = i / KZ, k = i - j * KZ;
    float w = (k < HID) ? Wih[j * HID + k] : Whh[j * HID + (k - HID)];
    __nv_bfloat16 hi = __float2bfloat16(w);
    g_Wghi[i] = hi;
    g_Wglo[i] = __float2bfloat16(w - __bfloat162float(hi));
}
__global__ void k_init(const float* __restrict__ emb) {
    int i = blockIdx.x * 256 + threadIdx.x;
    if (i >= NB * HID) return;
    int b = i / HID, k = i - b * HID;
    g_h[i] = 0.f; g_c[i] = 0.f;
    float x = emb[HID + k];  // SOS token = row 1
    __nv_bfloat16 hi = __float2bfloat16(x);
    g_zhi[b * KZ + k] = hi;
    g_zlo[b * KZ + k] = __float2bfloat16(x - __bfloat162float(hi));
    g_zhi[b * KZ + HID + k] = __float2bfloat16(0.f);
    g_zlo[b * KZ + HID + k] = __float2bfloat16(0.f);
}

// ---- gates GEMM: partial [3072,64] per K-part ----
__global__ void __launch_bounds__(128) k_gates() {
    char* smem = dyn_smem;
    uint32_t sb = smem_u32(smem);
    int jt = blockIdx.x / GPARTS, part = blockIdx.x % GPARTS;
    long k0 = (long)part * GK;
    mma_mainloop(smem, sb, g_Wghi + k0, g_Wglo + k0, KZ, (long)jt * 128,
                 g_zhi + k0, g_zlo + k0, KZ, GK / 32);
    const float* C = (const float*)smem;
    int j = jt * 128 + threadIdx.x;
    float4* o = (float4*)(g_gatesP + ((size_t)part * NGATE + j) * 64);
    const float* row = C + threadIdx.x * 65;
#pragma unroll
    for (int b = 0; b < 64; b += 4)
        o[b >> 2] = make_float4(row[b], row[b + 1], row[b + 2], row[b + 3]);
}

// ---- LSTM elementwise ----
__global__ void k_update(const float* __restrict__ b_ih, const float* __restrict__ b_hh) {
    int i = blockIdx.x * 256 + threadIdx.x;
    if (i >= NB * HID) return;
    int k = i >> 6, b = i & 63;
    float xi = b_ih[k] + b_hh[k];
    float xf = b_ih[HID + k] + b_hh[HID + k];
    float xg = b_ih[2 * HID + k] + b_hh[2 * HID + k];
    float xo = b_ih[3 * HID + k] + b_hh[3 * HID + k];
#pragma unroll
    for (int p = 0; p < GPARTS; p++) {
        size_t base = (size_t)p * NGATE;
        xi += g_gatesP[(base + k) * 64 + b];
        xf += g_gatesP[(base + HID + k) * 64 + b];
        xg += g_gatesP[(base + 2 * HID + k) * 64 + b];
        xo += g_gatesP[(base + 3 * HID + k) * 64 + b];
    }
    float ig = 1.f / (1.f + expf(-xi));
    float fg = 1.f / (1.f + expf(-xf));
    float gg = tanhf(xg);
    float og = 1.f / (1.f + expf(-xo));
    int hidx = b * HID + k;
    float c = fg * g_c[hidx] + ig * gg;
    float h = og * tanhf(c);
    g_c[hidx] = c; g_h[hidx] = h;
    __nv_bfloat16 hi = __float2bfloat16(h);
    __nv_bfloat16 lo = __float2bfloat16(h - __bfloat162float(hi));
    g_hhi[hidx] = hi; g_hlo[hidx] = lo;
    g_zhi[b * KZ + HID + k] = hi;  // z second half for next step's gates
    g_zlo[b * KZ + HID + k] = lo;
}

// ---- logits GEMM + bias + store + partial argmax ----
__global__ void __launch_bounds__(128) k_logits(const float* __restrict__ b_out,
                                                float* __restrict__ out, int t) {
    char* smem = dyn_smem;
    uint32_t sb = smem_u32(smem);
    long v0 = (long)blockIdx.x * 128;
    mma_mainloop(smem, sb, g_Wouthi, g_Woutlo, HID, v0,
                 g_hhi, g_hlo, HID, HID / 32);
    const float* C = (const float*)smem;

    int wid = threadIdx.x >> 5, lane = threadIdx.x & 31;
    int v = (int)v0 + threadIdx.x;
    bool valid = (v < VOCAB);
    float bias = valid ? b_out[v] : NEG_BIG;
    float* op = out + (size_t)t * VOCAB + v;
    const float* row = C + threadIdx.x * 65;
    float* swv = (float*)(smem + OFF_SWV);
    int*   swi = (int*)(smem + OFF_SWI);

#pragma unroll 8
    for (int b = 0; b < 64; b++) {
        float val = row[b] + bias;
        if (valid) op[(size_t)b * ((size_t)MAXLEN * VOCAB)] = val;
        float rm = val; int ri = v;
#pragma unroll
        for (int off = 16; off; off >>= 1) {
            float ov = __shfl_down_sync(0xffffffffu, rm, off);
            int oi = __shfl_down_sync(0xffffffffu, ri, off);
            if (ov > rm || (ov == rm && oi < ri)) { rm = ov; ri = oi; }
        }
        if (lane == 0) { swv[wid * 64 + b] = rm; swi[wid * 64 + b] = ri; }
    }
    __syncthreads();
    if (threadIdx.x < 64) {
        int b = threadIdx.x;
        float bm = swv[b]; int bi = swi[b];
#pragma unroll
        for (int w2 = 1; w2 < 4; w2++) {
            float ov = swv[w2 * 64 + b]; int oi = swi[w2 * 64 + b];
            if (ov > bm || (ov == bm && oi < bi)) { bm = ov; bi = oi; }
        }
        g_pmax[blockIdx.x * 64 + b] = bm;
        g_pidx[blockIdx.x * 64 + b] = bi;
    }
}

// ---- final argmax reduce + build z first half ----
__global__ void k_argmax_z(const float* __restrict__ emb) {
    int b = blockIdx.x, tid = threadIdx.x;  // 128 threads
    __shared__ float sv[128];
    __shared__ int si[128];
    float m = NEG_BIG; int mi = 0x7fffffff;
    for (int p = tid; p < VTILES; p += 128) {
        float v = g_pmax[p * 64 + b];
        int i2 = g_pidx[p * 64 + b];
        if (v > m || (v == m && i2 < mi)) { m = v; mi = i2; }
    }
    sv[tid] = m; si[tid] = mi;
    __syncthreads();
    for (int s = 64; s > 0; s >>= 1) {
        if (tid < s) {
            float ov = sv[tid + s]; int oi = si[tid + s];
            if (ov > sv[tid] || (ov == sv[tid] && oi < si[tid])) { sv[tid] = ov; si[tid] = oi; }
        }
        __syncthreads();
    }
    int tok = si[0];
    for (int k = tid; k < HID; k += 128) {
        float x = emb[(size_t)tok * HID + k];
        __nv_bfloat16 hi = __float2bfloat16(x);
        g_zhi[b * KZ + k] = hi;
        g_zlo[b * KZ + k] = __float2bfloat16(x - __bfloat162float(hi));
    }
}

// ---- final h,c copy into output tail ----
__global__ void k_finalhc(float* __restrict__ out) {
    int i = blockIdx.x * 256 + threadIdx.x;
    if (i >= NB * HID) return;
    size_t base = (size_t)NB * MAXLEN * VOCAB;
    out[base + i] = g_h[i];
    out[base + (size_t)NB * HID + i] = g_c[i];
}

extern "C" void kernel_launch(void* const* d_in, const int* in_sizes, int n_in,
                              void* d_out, int out_size) {
    const float* emb   = (const float*)d_in[1];
    const float* W_ih  = (const float*)d_in[2];
    const float* W_hh  = (const float*)d_in[3];
    const float* b_ih  = (const float*)d_in[4];
    const float* b_hh  = (const float*)d_in[5];
    const float* W_out = (const float*)d_in[6];
    const float* b_out = (const float*)d_in[7];
    float* out = (float*)d_out;

    cudaFuncSetAttribute(k_gates,  cudaFuncAttributeMaxDynamicSharedMemorySize, SMEM_BYTES);
    cudaFuncSetAttribute(k_logits, cudaFuncAttributeMaxDynamicSharedMemorySize, SMEM_BYTES);

    k_split_wout<<<(int)(((size_t)VPAD * HID + 255) / 256), 256>>>(W_out);
    k_split_wg<<<(NGATE * KZ + 255) / 256, 256>>>(W_ih, W_hh);
    k_init<<<(NB * HID + 255) / 256, 256>>>(emb);

    for (int t = 0; t < MAXLEN; t++) {
        k_gates<<<GTILES * GPARTS, 128, SMEM_BYTES>>>();
        k_update<<<(NB * HID + 255) / 256, 256>>>(b_ih, b_hh);
        k_logits<<<VTILES, 128, SMEM_BYTES>>>(b_out, out, t);
        k_argmax_z<<<NB, 128>>>(emb);
    }
    k_finalhc<<<(NB * HID + 255) / 256, 256>>>(out);
}

// round 10
// speedup vs baseline: 1.0032x; 1.0032x over previous
#include <cuda_runtime.h>
#include <cuda_bf16.h>
#include <cstdint>
#include <cstddef>

#define VOCAB   50257
#define VPAD    50304
#define HID     768
#define NGATE   3072
#define KZ      1536
#define MAXLEN  32
#define NB      64
#define VTILES  393
#define GPARTS  6
#define GK      256
#define GTILES  24

#define NSTAGE      3
#define STAGE_BYTES 24576
#define SA_HI 0
#define SA_LO 8192
#define SB_HI 16384
#define SB_LO 20480
#define SMEM_BYTES  73728
#define OFF_SWV 36864
#define OFF_SWI 38912
#define NEG_BIG (-3.402823466e38f)

// ---- device scratch (static; no allocs allowed) ----
__device__ __align__(256) __nv_bfloat16 g_Wouthi[(size_t)VPAD * HID];
__device__ __align__(256) __nv_bfloat16 g_Woutlo[(size_t)VPAD * HID];
__device__ __align__(256) __nv_bfloat16 g_Wghi[NGATE * KZ];
__device__ __align__(256) __nv_bfloat16 g_Wglo[NGATE * KZ];
__device__ __align__(256) float g_h[NB * HID];
__device__ __align__(256) float g_c[NB * HID];
__device__ __align__(256) __nv_bfloat16 g_hhi[NB * HID];
__device__ __align__(256) __nv_bfloat16 g_hlo[NB * HID];
__device__ __align__(256) __nv_bfloat16 g_zhi[NB * KZ];
__device__ __align__(256) __nv_bfloat16 g_zlo[NB * KZ];
__device__ __align__(256) float g_gatesP[GPARTS * NGATE * NB];
__device__ __align__(256) float g_pmax[VTILES * NB];
__device__ __align__(256) int   g_pidx[VTILES * NB];

// ---- helpers ----
__device__ __forceinline__ uint32_t smem_u32(const void* p) {
    uint32_t a;
    asm("{ .reg .u64 t; cvta.to.shared.u64 t, %1; cvt.u32.u64 %0, t; }" : "=r"(a) : "l"(p));
    return a;
}
#define SWZ64(x) ((uint32_t)(x) ^ ((((uint32_t)(x)) >> 3) & 0x30u))

__device__ __forceinline__ void cpasync16(uint32_t sa, const void* g) {
    asm volatile("cp.async.cg.shared.global [%0], [%1], 16;" :: "r"(sa), "l"(g));
}
__device__ __forceinline__ void cp_commit() { asm volatile("cp.async.commit_group;" ::: "memory"); }
__device__ __forceinline__ void cp_wait1()  { asm volatile("cp.async.wait_group 1;" ::: "memory"); }

__device__ __forceinline__ void ldsm4(uint32_t* r, uint32_t addr) {
    asm volatile("ldmatrix.sync.aligned.m8n8.x4.shared.b16 {%0,%1,%2,%3}, [%4];"
        : "=r"(r[0]), "=r"(r[1]), "=r"(r[2]), "=r"(r[3]) : "r"(addr));
}
__device__ __forceinline__ void mma16816(float* c, const uint32_t* a, const uint32_t* b) {
    asm volatile("mma.sync.aligned.m16n8k16.row.col.f32.bf16.bf16.f32 "
        "{%0,%1,%2,%3}, {%4,%5,%6,%7}, {%8,%9}, {%0,%1,%2,%3};"
        : "+f"(c[0]), "+f"(c[1]), "+f"(c[2]), "+f"(c[3])
        : "r"(a[0]), "r"(a[1]), "r"(a[2]), "r"(a[3]), "r"(b[0]), "r"(b[1]));
}

extern __shared__ __align__(1024) char dyn_smem[];

// load one K=32 chunk (A: 128x32 hi+lo, B: 64x32 hi+lo) into stage. 256 threads.
__device__ __forceinline__ void load_chunk(uint32_t sb, int stage,
    const __nv_bfloat16* __restrict__ Ahi, const __nv_bfloat16* __restrict__ Alo,
    long lda, long rowA0,
    const __nv_bfloat16* __restrict__ Bhi, const __nv_bfloat16* __restrict__ Blo,
    long ldb, long kc, int tid)
{
    uint32_t st = sb + (uint32_t)stage * STAGE_BYTES;
#pragma unroll
    for (int i = 0; i < 2; i++) {           // A: 128 rows x 4 x 16B = 512 xfers
        int u = tid + i * 256;
        int r = u >> 2, c4 = u & 3;
        size_t g = (size_t)(rowA0 + r) * lda + kc + c4 * 8;
        uint32_t so = SWZ64(r * 64 + c4 * 16);
        cpasync16(st + SA_HI + so, Ahi + g);
        cpasync16(st + SA_LO + so, Alo + g);
    }
    {                                       // B: 64 rows x 4 x 16B = 256 xfers
        int r = tid >> 2, c4 = tid & 3;
        size_t g = (size_t)r * ldb + kc + c4 * 8;
        uint32_t so = SWZ64(r * 64 + c4 * 16);
        cpasync16(st + SB_HI + so, Bhi + g);
        cpasync16(st + SB_LO + so, Blo + g);
    }
}

// C[128,64] = sum_K (Ahi+Alo)[128,K] x (Bhi+Blo)[64,K]^T  (3 split GEMMs, lo*lo dropped)
// 8 warps, warp = 16 rows x 64 cols. Result in smem C[m][b], row stride 65 floats.
__device__ __forceinline__ void mma_mainloop(
    char* smem, uint32_t sb,
    const __nv_bfloat16* __restrict__ Ahi, const __nv_bfloat16* __restrict__ Alo,
    long lda, long rowA0,
    const __nv_bfloat16* __restrict__ Bhi, const __nv_bfloat16* __restrict__ Blo,
    long ldb, int nchunks)
{
    const int tid = threadIdx.x;
    const int wid = tid >> 5, lane = tid & 31;
    float acc[8][4];
#pragma unroll
    for (int nt = 0; nt < 8; nt++)
#pragma unroll
        for (int r = 0; r < 4; r++) acc[nt][r] = 0.f;

    const int a_r = lane & 15;
    const int a_c = (lane >> 4) << 4;
    const int b_r = (lane & 7) + ((lane & 16) >> 1);
    const int b_c = (lane & 8) << 1;

    load_chunk(sb, 0, Ahi, Alo, lda, rowA0, Bhi, Blo, ldb, 0, tid);
    cp_commit();
    load_chunk(sb, 1, Ahi, Alo, lda, rowA0, Bhi, Blo, ldb, 32, tid);
    cp_commit();

    for (int ch = 0; ch < nchunks; ch++) {
        cp_wait1();
        __syncthreads();
        if (ch + 2 < nchunks)
            load_chunk(sb, (ch + 2) % NSTAGE, Ahi, Alo, lda, rowA0,
                       Bhi, Blo, ldb, (long)(ch + 2) * 32, tid);
        cp_commit();

        uint32_t st = sb + (uint32_t)(ch % NSTAGE) * STAGE_BYTES;
#pragma unroll
        for (int ks = 0; ks < 2; ks++) {
            const int kb = ks * 32;
            uint32_t ah[4], al[4];
            {
                uint32_t so = SWZ64((wid * 16 + a_r) * 64 + kb + a_c);
                ldsm4(ah, st + SA_HI + so);
                ldsm4(al, st + SA_LO + so);
            }
            {   // B hi: terms ah*bh and al*bh
                uint32_t bh[4][4];
#pragma unroll
                for (int p = 0; p < 4; p++) {
                    uint32_t so = SWZ64((p * 16 + b_r) * 64 + kb + b_c);
                    ldsm4(bh[p], st + SB_HI + so);
                }
#pragma unroll
                for (int p = 0; p < 4; p++) {
                    mma16816(acc[2 * p],     ah, &bh[p][0]);
                    mma16816(acc[2 * p + 1], ah, &bh[p][2]);
                }
#pragma unroll
                for (int p = 0; p < 4; p++) {
                    mma16816(acc[2 * p],     al, &bh[p][0]);
                    mma16816(acc[2 * p + 1], al, &bh[p][2]);
                }
            }
            {   // B lo: term ah*bl
                uint32_t bl[4][4];
#pragma unroll
                for (int p = 0; p < 4; p++) {
                    uint32_t so = SWZ64((p * 16 + b_r) * 64 + kb + b_c);
                    ldsm4(bl[p], st + SB_LO + so);
                }
#pragma unroll
                for (int p = 0; p < 4; p++) {
                    mma16816(acc[2 * p],     ah, &bl[p][0]);
                    mma16816(acc[2 * p + 1], ah, &bl[p][2]);
                }
            }
        }
    }
    __syncthreads();
    float* C = (float*)smem;
#pragma unroll
    for (int nt = 0; nt < 8; nt++)
#pragma unroll
        for (int r = 0; r < 4; r++) {
            int m = wid * 16 + (lane >> 2) + ((r & 2) ? 8 : 0);
            int n = nt * 8 + 2 * (lane & 3) + (r & 1);
            C[m * 65 + n] = acc[nt][r];
        }
    __syncthreads();
}

// ---- prep kernels ----
__global__ void k_split_wout(const float* __restrict__ W) {
    size_t i = (size_t)blockIdx.x * 256 + threadIdx.x;
    if (i >= (size_t)VPAD * HID) return;
    float w = (i < (size_t)VOCAB * HID) ? W[i] : 0.f;
    __nv_bfloat16 hi = __float2bfloat16(w);
    g_Wouthi[i] = hi;
    g_Woutlo[i] = __float2bfloat16(w - __bfloat162float(hi));
}
__global__ void k_split_wg(const float* __restrict__ Wih, const float* __restrict__ Whh) {
    int i = blockIdx.x * 256 + threadIdx.x;
    if (i >= NGATE * KZ) return;
    int j = i / KZ, k = i - j * KZ;
    float w = (k < HID) ? Wih[j * HID + k] : Whh[j * HID + (k - HID)];
    __nv_bfloat16 hi = __float2bfloat16(w);
    g_Wghi[i] = hi;
    g_Wglo[i] = __float2bfloat16(w - __bfloat162float(hi));
}
__global__ void k_init(const float* __restrict__ emb) {
    int i = blockIdx.x * 256 + threadIdx.x;
    if (i >= NB * HID) return;
    int b = i / HID, k = i - b * HID;
    g_h[i] = 0.f; g_c[i] = 0.f;
    float x = emb[HID + k];  // SOS token = row 1
    __nv_bfloat16 hi = __float2bfloat16(x);
    g_zhi[b * KZ + k] = hi;
    g_zlo[b * KZ + k] = __float2bfloat16(x - __bfloat162float(hi));
    g_zhi[b * KZ + HID + k] = __float2bfloat16(0.f);
    g_zlo[b * KZ + HID + k] = __float2bfloat16(0.f);
}

// ---- gates GEMM: partial [3072,64] per K-part ----
__global__ void __launch_bounds__(256, 3) k_gates() {
    char* smem = dyn_smem;
    uint32_t sb = smem_u32(smem);
    int jt = blockIdx.x / GPARTS, part = blockIdx.x % GPARTS;
    long k0 = (long)part * GK;
    mma_mainloop(smem, sb, g_Wghi + k0, g_Wglo + k0, KZ, (long)jt * 128,
                 g_zhi + k0, g_zlo + k0, KZ, GK / 32);
    const float* C = (const float*)smem;
    int r = threadIdx.x >> 1, half = threadIdx.x & 1;
    int j = jt * 128 + r;
    float4* o = (float4*)(g_gatesP + ((size_t)part * NGATE + j) * 64 + half * 32);
    const float* row = C + r * 65 + half * 32;
#pragma unroll
    for (int b = 0; b < 32; b += 4)
        o[b >> 2] = make_float4(row[b], row[b + 1], row[b + 2], row[b + 3]);
}

// ---- LSTM elementwise ----
__global__ void k_update(const float* __restrict__ b_ih, const float* __restrict__ b_hh) {
    int i = blockIdx.x * 256 + threadIdx.x;
    if (i >= NB * HID) return;
    int k = i >> 6, b = i & 63;
    float xi = b_ih[k] + b_hh[k];
    float xf = b_ih[HID + k] + b_hh[HID + k];
    float xg = b_ih[2 * HID + k] + b_hh[2 * HID + k];
    float xo = b_ih[3 * HID + k] + b_hh[3 * HID + k];
#pragma unroll
    for (int p = 0; p < GPARTS; p++) {
        size_t base = (size_t)p * NGATE;
        xi += g_gatesP[(base + k) * 64 + b];
        xf += g_gatesP[(base + HID + k) * 64 + b];
        xg += g_gatesP[(base + 2 * HID + k) * 64 + b];
        xo += g_gatesP[(base + 3 * HID + k) * 64 + b];
    }
    float ig = 1.f / (1.f + expf(-xi));
    float fg = 1.f / (1.f + expf(-xf));
    float gg = tanhf(xg);
    float og = 1.f / (1.f + expf(-xo));
    int hidx = b * HID + k;
    float c = fg * g_c[hidx] + ig * gg;
    float h = og * tanhf(c);
    g_c[hidx] = c; g_h[hidx] = h;
    __nv_bfloat16 hi = __float2bfloat16(h);
    __nv_bfloat16 lo = __float2bfloat16(h - __bfloat162float(hi));
    g_hhi[hidx] = hi; g_hlo[hidx] = lo;
    g_zhi[b * KZ + HID + k] = hi;  // z second half for next step's gates
    g_zlo[b * KZ + HID + k] = lo;
}

// ---- logits GEMM + bias + store + partial argmax ----
__global__ void __launch_bounds__(256, 3) k_logits(const float* __restrict__ b_out,
                                                   float* __restrict__ out, int t) {
    char* smem = dyn_smem;
    uint32_t sb = smem_u32(smem);
    long v0 = (long)blockIdx.x * 128;
    mma_mainloop(smem, sb, g_Wouthi, g_Woutlo, HID, v0,
                 g_hhi, g_hlo, HID, HID / 32);
    const float* C = (const float*)smem;

    int wid = threadIdx.x >> 5, lane = threadIdx.x & 31;
    int vloc = threadIdx.x & 127;
    int grp = threadIdx.x >> 7;           // b-half: 0 -> b 0..31, 1 -> b 32..63
    int v = (int)v0 + vloc;
    bool valid = (v < VOCAB);
    float bias = valid ? b_out[v] : NEG_BIG;
    float* op = out + (size_t)t * VOCAB + v;
    const float* row = C + vloc * 65 + grp * 32;
    float* swv = (float*)(smem + OFF_SWV);
    int*   swi = (int*)(smem + OFF_SWI);

#pragma unroll 8
    for (int b = 0; b < 32; b++) {
        int bb = grp * 32 + b;
        float val = row[b] + bias;
        if (valid) op[(size_t)bb * ((size_t)MAXLEN * VOCAB)] = val;
        float rm = val; int ri = v;
#pragma unroll
        for (int off = 16; off; off >>= 1) {
            float ov = __shfl_down_sync(0xffffffffu, rm, off);
            int oi = __shfl_down_sync(0xffffffffu, ri, off);
            if (ov > rm || (ov == rm && oi < ri)) { rm = ov; ri = oi; }
        }
        if (lane == 0) { swv[wid * 32 + b] = rm; swi[wid * 32 + b] = ri; }
    }
    __syncthreads();
    if (threadIdx.x < 64) {
        int b = threadIdx.x;
        int g0 = (b >> 5) * 4;            // warps g0..g0+3 hold this b-half
        int e = b & 31;
        float bm = swv[g0 * 32 + e]; int bi = swi[g0 * 32 + e];
#pragma unroll
        for (int w2 = 1; w2 < 4; w2++) {
            float ov = swv[(g0 + w2) * 32 + e]; int oi = swi[(g0 + w2) * 32 + e];
            if (ov > bm || (ov == bm && oi < bi)) { bm = ov; bi = oi; }
        }
        g_pmax[blockIdx.x * 64 + b] = bm;
        g_pidx[blockIdx.x * 64 + b] = bi;
    }
}

// ---- final argmax reduce + build z first half ----
__global__ void k_argmax_z(const float* __restrict__ emb) {
    int b = blockIdx.x, tid = threadIdx.x;  // 128 threads
    __shared__ float sv[128];
    __shared__ int si[128];
    float m = NEG_BIG; int mi = 0x7fffffff;
    for (int p = tid; p < VTILES; p += 128) {
        float v = g_pmax[p * 64 + b];
        int i2 = g_pidx[p * 64 + b];
        if (v > m || (v == m && i2 < mi)) { m = v; mi = i2; }
    }
    sv[tid] = m; si[tid] = mi;
    __syncthreads();
    for (int s = 64; s > 0; s >>= 1) {
        if (tid < s) {
            float ov = sv[tid + s]; int oi = si[tid + s];
            if (ov > sv[tid] || (ov == sv[tid] && oi < si[tid])) { sv[tid] = ov; si[tid] = oi; }
        }
        __syncthreads();
    }
    int tok = si[0];
    for (int k = tid; k < HID; k += 128) {
        float x = emb[(size_t)tok * HID + k];
        __nv_bfloat16 hi = __float2bfloat16(x);
        g_zhi[b * KZ + k] = hi;
        g_zlo[b * KZ + k] = __float2bfloat16(x - __bfloat162float(hi));
    }
}

// ---- final h,c copy into output tail ----
__global__ void k_finalhc(float* __restrict__ out) {
    int i = blockIdx.x * 256 + threadIdx.x;
    if (i >= NB * HID) return;
    size_t base = (size_t)NB * MAXLEN * VOCAB;
    out[base + i] = g_h[i];
    out[base + (size_t)NB * HID + i] = g_c[i];
}

extern "C" void kernel_launch(void* const* d_in, const int* in_sizes, int n_in,
                              void* d_out, int out_size) {
    const float* emb   = (const float*)d_in[1];
    const float* W_ih  = (const float*)d_in[2];
    const float* W_hh  = (const float*)d_in[3];
    const float* b_ih  = (const float*)d_in[4];
    const float* b_hh  = (const float*)d_in[5];
    const float* W_out = (const float*)d_in[6];
    const float* b_out = (const float*)d_in[7];
    float* out = (float*)d_out;

    cudaFuncSetAttribute(k_gates,  cudaFuncAttributeMaxDynamicSharedMemorySize, SMEM_BYTES);
    cudaFuncSetAttribute(k_logits, cudaFuncAttributeMaxDynamicSharedMemorySize, SMEM_BYTES);

    k_split_wout<<<(int)(((size_t)VPAD * HID + 255) / 256), 256>>>(W_out);
    k_split_wg<<<(NGATE * KZ + 255) / 256, 256>>>(W_ih, W_hh);
    k_init<<<(NB * HID + 255) / 256, 256>>>(emb);

    for (int t = 0; t < MAXLEN; t++) {
        k_gates<<<GTILES * GPARTS, 256, SMEM_BYTES>>>();
        k_update<<<(NB * HID + 255) / 256, 256>>>(b_ih, b_hh);
        k_logits<<<VTILES, 256, SMEM_BYTES>>>(b_out, out, t);
        k_argmax_z<<<NB, 128>>>(emb);
    }
    k_finalhc<<<(NB * HID + 255) / 256, 256>>>(out);
}

// round 11
// speedup vs baseline: 1.1611x; 1.1574x over previous
#include <cuda_runtime.h>
#include <cuda_bf16.h>
#include <cstdint>
#include <cstddef>

#define VOCAB   50257
#define VPAD    50304
#define HID     768
#define NGATE   3072
#define KZ      1536
#define MAXLEN  32
#define NB      64
#define VTILES  393
#define GPARTS  6
#define GTILES  24
#define NCH_W   24            /* K-chunks per 128-row W tile (768/32)  */
#define NCH_Z   48            /* K-chunks of z (1536/32)               */

#define NSTAGE      3
#define STAGE_BYTES 24576
#define SA_HI 0
#define SA_LO 8192
#define SB_HI 16384
#define SB_LO 20480
#define MBAR_OFF    73728
#define SMEM_BYTES  73984
#define OFF_SWV 36864
#define OFF_SWI 38912
#define NEG_BIG (-3.402823466e38f)

// ---- device scratch (static; no allocs). Weight/act tiles stored PRE-SWIZZLED:
// A-tile = 8KB: 128 rows x 64B (32 bf16), SW64 swizzle. B-tile = 4KB: 64 rows x 64B.
__device__ __align__(256) unsigned char g_Wouthi[(size_t)VTILES * NCH_W * 8192];
__device__ __align__(256) unsigned char g_Woutlo[(size_t)VTILES * NCH_W * 8192];
__device__ __align__(256) unsigned char g_Wghi[(size_t)GTILES * NCH_Z * 8192];
__device__ __align__(256) unsigned char g_Wglo[(size_t)GTILES * NCH_Z * 8192];
__device__ __align__(256) unsigned char g_hhi[NCH_W * 4096];
__device__ __align__(256) unsigned char g_hlo[NCH_W * 4096];
__device__ __align__(256) unsigned char g_zhi[NCH_Z * 4096];
__device__ __align__(256) unsigned char g_zlo[NCH_Z * 4096];
__device__ __align__(256) float g_h[NB * HID];
__device__ __align__(256) float g_c[NB * HID];
__device__ __align__(256) float g_gatesP[GPARTS * NGATE * NB];
__device__ __align__(256) float g_pmax[VTILES * NB];
__device__ __align__(256) int   g_pidx[VTILES * NB];

// ---- helpers ----
__device__ __forceinline__ uint32_t smem_u32(const void* p) {
    uint32_t a;
    asm("{ .reg .u64 t; cvta.to.shared.u64 t, %1; cvt.u32.u64 %0, t; }" : "=r"(a) : "l"(p));
    return a;
}
#define SWZ64(x) ((uint32_t)(x) ^ ((((uint32_t)(x)) >> 3) & 0x30u))

#define MBAR_INIT(a, c) asm volatile("mbarrier.init.shared.b64 [%0], %1;" :: "r"(a), "r"(c) : "memory")
#define MBAR_EXPECT(a, tx) asm volatile("mbarrier.arrive.expect_tx.shared.b64 _, [%0], %1;" :: "r"(a), "r"((uint32_t)(tx)) : "memory")
#define MBAR_WAIT(a, ph) do { \
    uint32_t _m = (a), _p = (ph), _d; \
    asm volatile("{ .reg .pred p; mbarrier.try_wait.parity.acquire.cta.shared::cta.b64 p, [%1], %2; selp.b32 %0,1,0,p; }" \
        : "=r"(_d) : "r"(_m), "r"(_p) : "memory"); \
    if (!_d) { \
        asm volatile("{ .reg .pred P1;\nWL_%=: mbarrier.try_wait.parity.acquire.cta.shared::cta.b64 P1, [%0], %1, 0x989680;\n@P1 bra.uni WD_%=;\nbra.uni WL_%=;\nWD_%=: }" \
            :: "r"(_m), "r"(_p) : "memory"); \
    } } while (0)

__device__ __forceinline__ void bulk_g2s(uint32_t sdst, const void* gsrc, uint32_t bytes, uint32_t mbar) {
    asm volatile("cp.async.bulk.shared::cluster.global.mbarrier::complete_tx::bytes [%0], [%1], %2, [%3];"
        :: "r"(sdst), "l"(gsrc), "r"(bytes), "r"(mbar) : "memory");
}

__device__ __forceinline__ void ldsm4(uint32_t* r, uint32_t addr) {
    asm volatile("ldmatrix.sync.aligned.m8n8.x4.shared.b16 {%0,%1,%2,%3}, [%4];"
        : "=r"(r[0]), "=r"(r[1]), "=r"(r[2]), "=r"(r[3]) : "r"(addr));
}
__device__ __forceinline__ void mma16816(float* c, const uint32_t* a, const uint32_t* b) {
    asm volatile("mma.sync.aligned.m16n8k16.row.col.f32.bf16.bf16.f32 "
        "{%0,%1,%2,%3}, {%4,%5,%6,%7}, {%8,%9}, {%0,%1,%2,%3};"
        : "+f"(c[0]), "+f"(c[1]), "+f"(c[2]), "+f"(c[3])
        : "r"(a[0]), "r"(a[1]), "r"(a[2]), "r"(a[3]), "r"(b[0]), "r"(b[1]));
}

extern __shared__ __align__(1024) char dyn_smem[];

// issue bulk loads for chunk ch into stage ch%3 (leader thread only)
__device__ __forceinline__ void issue_chunk(uint32_t sb, uint32_t mb, int ch,
    const unsigned char* Ahi, const unsigned char* Alo,
    const unsigned char* Bhi, const unsigned char* Blo)
{
    uint32_t st = sb + (uint32_t)(ch % NSTAGE) * STAGE_BYTES;
    uint32_t m = mb + 8u * (ch % NSTAGE);
    MBAR_EXPECT(m, STAGE_BYTES);
    bulk_g2s(st + SA_HI, Ahi + (size_t)ch * 8192, 8192, m);
    bulk_g2s(st + SA_LO, Alo + (size_t)ch * 8192, 8192, m);
    bulk_g2s(st + SB_HI, Bhi + (size_t)ch * 4096, 4096, m);
    bulk_g2s(st + SB_LO, Blo + (size_t)ch * 4096, 4096, m);
}

// C[128,64] = sum_K (Ahi+Alo)[128,K] x (Bhi+Blo)[64,K]^T  (3 split GEMMs, lo*lo dropped)
// 8 warps, warp = 16 rows x 64 cols. Result in smem C[m][b], row stride 65 floats.
__device__ __forceinline__ void mma_mainloop(
    char* smem, uint32_t sb,
    const unsigned char* Ahi, const unsigned char* Alo,
    const unsigned char* Bhi, const unsigned char* Blo, int nchunks)
{
    const int tid = threadIdx.x;
    const int wid = tid >> 5, lane = tid & 31;
    const uint32_t mb = sb + MBAR_OFF;
    float acc[8][4];
#pragma unroll
    for (int nt = 0; nt < 8; nt++)
#pragma unroll
        for (int r = 0; r < 4; r++) acc[nt][r] = 0.f;

    if (tid == 0) {
#pragma unroll
        for (int s = 0; s < NSTAGE; s++) MBAR_INIT(mb + 8u * s, 1);
        asm volatile("fence.mbarrier_init.release.cluster;" ::: "memory");
    }
    __syncthreads();
    if (tid == 0) {
        issue_chunk(sb, mb, 0, Ahi, Alo, Bhi, Blo);
        issue_chunk(sb, mb, 1, Ahi, Alo, Bhi, Blo);
    }

    const int a_r = lane & 15;
    const int a_c = (lane >> 4) << 4;
    const int b_r = (lane & 7) + ((lane & 16) >> 1);
    const int b_c = (lane & 8) << 1;

    for (int ch = 0; ch < nchunks; ch++) {
        MBAR_WAIT(mb + 8u * (ch % NSTAGE), (ch / NSTAGE) & 1);
        uint32_t st = sb + (uint32_t)(ch % NSTAGE) * STAGE_BYTES;
#pragma unroll
        for (int ks = 0; ks < 2; ks++) {
            const int kb = ks * 32;
            uint32_t ah[4], al[4];
            {
                uint32_t so = SWZ64((wid * 16 + a_r) * 64 + kb + a_c);
                ldsm4(ah, st + SA_HI + so);
                ldsm4(al, st + SA_LO + so);
            }
            {
                uint32_t bh[4][4];
#pragma unroll
                for (int p = 0; p < 4; p++) {
                    uint32_t so = SWZ64((p * 16 + b_r) * 64 + kb + b_c);
                    ldsm4(bh[p], st + SB_HI + so);
                }
#pragma unroll
                for (int p = 0; p < 4; p++) {
                    mma16816(acc[2 * p],     ah, &bh[p][0]);
                    mma16816(acc[2 * p + 1], ah, &bh[p][2]);
                }
#pragma unroll
                for (int p = 0; p < 4; p++) {
                    mma16816(acc[2 * p],     al, &bh[p][0]);
                    mma16816(acc[2 * p + 1], al, &bh[p][2]);
                }
            }
            {
                uint32_t bl[4][4];
#pragma unroll
                for (int p = 0; p < 4; p++) {
                    uint32_t so = SWZ64((p * 16 + b_r) * 64 + kb + b_c);
                    ldsm4(bl[p], st + SB_LO + so);
                }
#pragma unroll
                for (int p = 0; p < 4; p++) {
                    mma16816(acc[2 * p],     ah, &bl[p][0]);
                    mma16816(acc[2 * p + 1], ah, &bl[p][2]);
                }
            }
        }
        __syncthreads();   // all warps done with stage (ch-1)%3 == (ch+2)%3
        if (tid == 0 && ch + 2 < nchunks)
            issue_chunk(sb, mb, ch + 2, Ahi, Alo, Bhi, Blo);
    }
    float* C = (float*)smem;
#pragma unroll
    for (int nt = 0; nt < 8; nt++)
#pragma unroll
        for (int r = 0; r < 4; r++) {
            int m = wid * 16 + (lane >> 2) + ((r & 2) ? 8 : 0);
            int n = nt * 8 + 2 * (lane & 3) + (r & 1);
            C[m * 65 + n] = acc[nt][r];
        }
    __syncthreads();
}

// ---- prep kernels (write PRE-SWIZZLED tile layouts) ----
__global__ void k_split_wout(const float* __restrict__ W) {
    size_t i = (size_t)blockIdx.x * 256 + threadIdx.x;
    if (i >= (size_t)VPAD * HID) return;
    int v = (int)(i / HID), k = (int)(i - (size_t)v * HID);
    float w = (v < VOCAB) ? W[(size_t)v * HID + k] : 0.f;
    __nv_bfloat16 hi = __float2bfloat16(w);
    __nv_bfloat16 lo = __float2bfloat16(w - __bfloat162float(hi));
    size_t off = ((size_t)(v >> 7) * NCH_W + (k >> 5)) * 8192
               + SWZ64((v & 127) * 64 + (k & 31) * 2);
    *(__nv_bfloat16*)(g_Wouthi + off) = hi;
    *(__nv_bfloat16*)(g_Woutlo + off) = lo;
}
__global__ void k_split_wg(const float* __restrict__ Wih, const float* __restrict__ Whh) {
    int i = blockIdx.x * 256 + threadIdx.x;
    if (i >= NGATE * KZ) return;
    int j = i / KZ, k = i - j * KZ;
    float w = (k < HID) ? Wih[j * HID + k] : Whh[j * HID + (k - HID)];
    __nv_bfloat16 hi = __float2bfloat16(w);
    __nv_bfloat16 lo = __float2bfloat16(w - __bfloat162float(hi));
    size_t off = ((size_t)(j >> 7) * NCH_Z + (k >> 5)) * 8192
               + SWZ64((j & 127) * 64 + (k & 31) * 2);
    *(__nv_bfloat16*)(g_Wghi + off) = hi;
    *(__nv_bfloat16*)(g_Wglo + off) = lo;
}
__global__ void k_init(const float* __restrict__ emb) {
    int i = blockIdx.x * 256 + threadIdx.x;
    if (i >= NB * KZ) return;
    int b = i / KZ, k = i - b * KZ;
    if (k < HID) { g_h[b * HID + k] = 0.f; g_c[b * HID + k] = 0.f; }
    float x = (k < HID) ? emb[HID + k] : 0.f;   // SOS token = row 1; z[,768:]=h0=0
    __nv_bfloat16 hi = __float2bfloat16(x);
    __nv_bfloat16 lo = __float2bfloat16(x - __bfloat162float(hi));
    uint32_t off = (uint32_t)(k >> 5) * 4096 + SWZ64(b * 64 + (k & 31) * 2);
    *(__nv_bfloat16*)(g_zhi + off) = hi;
    *(__nv_bfloat16*)(g_zlo + off) = lo;
}

// ---- gates GEMM: partial [3072,64] per K-part ----
__global__ void __launch_bounds__(256, 3) k_gates() {
    char* smem = dyn_smem;
    uint32_t sb = smem_u32(smem);
    int jt = blockIdx.x / GPARTS, part = blockIdx.x % GPARTS;
    const unsigned char* Ahi = g_Wghi + ((size_t)jt * NCH_Z + part * 8) * 8192;
    const unsigned char* Alo = g_Wglo + ((size_t)jt * NCH_Z + part * 8) * 8192;
    const unsigned char* Bhi = g_zhi + (size_t)part * 8 * 4096;
    const unsigned char* Blo = g_zlo + (size_t)part * 8 * 4096;
    mma_mainloop(smem, sb, Ahi, Alo, Bhi, Blo, 8);
    const float* C = (const float*)smem;
    int r = threadIdx.x >> 1, half = threadIdx.x & 1;
    int j = jt * 128 + r;
    float4* o = (float4*)(g_gatesP + ((size_t)part * NGATE + j) * 64 + half * 32);
    const float* row = C + r * 65 + half * 32;
#pragma unroll
    for (int b = 0; b < 32; b += 4)
        o[b >> 2] = make_float4(row[b], row[b + 1], row[b + 2], row[b + 3]);
}

// ---- LSTM elementwise ----
__global__ void k_update(const float* __restrict__ b_ih, const float* __restrict__ b_hh) {
    int i = blockIdx.x * 256 + threadIdx.x;
    if (i >= NB * HID) return;
    int k = i >> 6, b = i & 63;
    float xi = b_ih[k] + b_hh[k];
    float xf = b_ih[HID + k] + b_hh[HID + k];
    float xg = b_ih[2 * HID + k] + b_hh[2 * HID + k];
    float xo = b_ih[3 * HID + k] + b_hh[3 * HID + k];
#pragma unroll
    for (int p = 0; p < GPARTS; p++) {
        size_t base = (size_t)p * NGATE;
        xi += g_gatesP[(base + k) * 64 + b];
        xf += g_gatesP[(base + HID + k) * 64 + b];
        xg += g_gatesP[(base + 2 * HID + k) * 64 + b];
        xo += g_gatesP[(base + 3 * HID + k) * 64 + b];
    }
    float ig = 1.f / (1.f + expf(-xi));
    float fg = 1.f / (1.f + expf(-xf));
    float gg = tanhf(xg);
    float og = 1.f / (1.f + expf(-xo));
    int hidx = b * HID + k;
    float c = fg * g_c[hidx] + ig * gg;
    float h = og * tanhf(c);
    g_c[hidx] = c; g_h[hidx] = h;
    __nv_bfloat16 hi = __float2bfloat16(h);
    __nv_bfloat16 lo = __float2bfloat16(h - __bfloat162float(hi));
    uint32_t off = (uint32_t)(k >> 5) * 4096 + SWZ64(b * 64 + (k & 31) * 2);
    *(__nv_bfloat16*)(g_hhi + off) = hi;
    *(__nv_bfloat16*)(g_hlo + off) = lo;
    uint32_t zoff = off + (uint32_t)NCH_W * 4096;   // z chunks 24..47
    *(__nv_bfloat16*)(g_zhi + zoff) = hi;
    *(__nv_bfloat16*)(g_zlo + zoff) = lo;
}

// ---- logits GEMM + bias + store + partial argmax ----
__global__ void __launch_bounds__(256, 3) k_logits(const float* __restrict__ b_out,
                                                   float* __restrict__ out, int t) {
    char* smem = dyn_smem;
    uint32_t sb = smem_u32(smem);
    const unsigned char* Ahi = g_Wouthi + (size_t)blockIdx.x * NCH_W * 8192;
    const unsigned char* Alo = g_Woutlo + (size_t)blockIdx.x * NCH_W * 8192;
    mma_mainloop(smem, sb, Ahi, Alo, g_hhi, g_hlo, NCH_W);
    const float* C = (const float*)smem;

    int wid = threadIdx.x >> 5, lane = threadIdx.x & 31;
    int vloc = threadIdx.x & 127;
    int grp = threadIdx.x >> 7;           // b-half: 0 -> b 0..31, 1 -> b 32..63
    int v = blockIdx.x * 128 + vloc;
    bool valid = (v < VOCAB);
    float bias = valid ? b_out[v] : NEG_BIG;
    float* op = out + (size_t)t * VOCAB + v;
    const float* row = C + vloc * 65 + grp * 32;
    float* swv = (float*)(smem + OFF_SWV);
    int*   swi = (int*)(smem + OFF_SWI);

#pragma unroll 8
    for (int b = 0; b < 32; b++) {
        int bb = grp * 32 + b;
        float val = row[b] + bias;
        if (valid) op[(size_t)bb * ((size_t)MAXLEN * VOCAB)] = val;
        float rm = val; int ri = v;
#pragma unroll
        for (int off = 16; off; off >>= 1) {
            float ov = __shfl_down_sync(0xffffffffu, rm, off);
            int oi = __shfl_down_sync(0xffffffffu, ri, off);
            if (ov > rm || (ov == rm && oi < ri)) { rm = ov; ri = oi; }
        }
        if (lane == 0) { swv[wid * 32 + b] = rm; swi[wid * 32 + b] = ri; }
    }
    __syncthreads();
    if (threadIdx.x < 64) {
        int b = threadIdx.x;
        int g0 = (b >> 5) * 4;
        int e = b & 31;
        float bm = swv[g0 * 32 + e]; int bi = swi[g0 * 32 + e];
#pragma unroll
        for (int w2 = 1; w2 < 4; w2++) {
            float ov = swv[(g0 + w2) * 32 + e]; int oi = swi[(g0 + w2) * 32 + e];
            if (ov > bm || (ov == bm && oi < bi)) { bm = ov; bi = oi; }
        }
        g_pmax[blockIdx.x * 64 + b] = bm;
        g_pidx[blockIdx.x * 64 + b] = bi;
    }
}

// ---- final argmax reduce + build z first half ----
__global__ void k_argmax_z(const float* __restrict__ emb) {
    int b = blockIdx.x, tid = threadIdx.x;  // 128 threads
    __shared__ float sv[128];
    __shared__ int si[128];
    float m = NEG_BIG; int mi = 0x7fffffff;
    for (int p = tid; p < VTILES; p += 128) {
        float v = g_pmax[p * 64 + b];
        int i2 = g_pidx[p * 64 + b];
        if (v > m || (v == m && i2 < mi)) { m = v; mi = i2; }
    }
    sv[tid] = m; si[tid] = mi;
    __syncthreads();
    for (int s = 64; s > 0; s >>= 1) {
        if (tid < s) {
            float ov = sv[tid + s]; int oi = si[tid + s];
            if (ov > sv[tid] || (ov == sv[tid] && oi < si[tid])) { sv[tid] = ov; si[tid] = oi; }
        }
        __syncthreads();
    }
    int tok = si[0];
    for (int k = tid; k < HID; k += 128) {
        float x = emb[(size_t)tok * HID + k];
        __nv_bfloat16 hi = __float2bfloat16(x);
        __nv_bfloat16 lo = __float2bfloat16(x - __bfloat162float(hi));
        uint32_t off = (uint32_t)(k >> 5) * 4096 + SWZ64(b * 64 + (k & 31) * 2);
        *(__nv_bfloat16*)(g_zhi + off) = hi;
        *(__nv_bfloat16*)(g_zlo + off) = lo;
    }
}

// ---- final h,c copy into output tail ----
__global__ void k_finalhc(float* __restrict__ out) {
    int i = blockIdx.x * 256 + threadIdx.x;
    if (i >= NB * HID) return;
    size_t base = (size_t)NB * MAXLEN * VOCAB;
    out[base + i] = g_h[i];
    out[base + (size_t)NB * HID + i] = g_c[i];
}

extern "C" void kernel_launch(void* const* d_in, const int* in_sizes, int n_in,
                              void* d_out, int out_size) {
    const float* emb   = (const float*)d_in[1];
    const float* W_ih  = (const float*)d_in[2];
    const float* W_hh  = (const float*)d_in[3];
    const float* b_ih  = (const float*)d_in[4];
    const float* b_hh  = (const float*)d_in[5];
    const float* W_out = (const float*)d_in[6];
    const float* b_out = (const float*)d_in[7];
    float* out = (float*)d_out;

    cudaFuncSetAttribute(k_gates,  cudaFuncAttributeMaxDynamicSharedMemorySize, SMEM_BYTES);
    cudaFuncSetAttribute(k_logits, cudaFuncAttributeMaxDynamicSharedMemorySize, SMEM_BYTES);

    k_split_wout<<<(int)(((size_t)VPAD * HID + 255) / 256), 256>>>(W_out);
    k_split_wg<<<(NGATE * KZ + 255) / 256, 256>>>(W_ih, W_hh);
    k_init<<<(NB * KZ + 255) / 256, 256>>>(emb);

    for (int t = 0; t < MAXLEN; t++) {
        k_gates<<<GTILES * GPARTS, 256, SMEM_BYTES>>>();
        k_update<<<(NB * HID + 255) / 256, 256>>>(b_ih, b_hh);
        k_logits<<<VTILES, 256, SMEM_BYTES>>>(b_out, out, t);
        k_argmax_z<<<NB, 128>>>(emb);
    }
    k_finalhc<<<(NB * HID + 255) / 256, 256>>>(out);
}

// round 12
// speedup vs baseline: 1.1799x; 1.0163x over previous
#include <cuda_runtime.h>
#include <cuda_bf16.h>
#include <cstdint>
#include <cstddef>

#define VOCAB   50257
#define VPAD    50304
#define HID     768
#define NGATE   3072
#define KZ      1536
#define MAXLEN  32
#define NB      64
#define VTILES  393
#define GPARTS  6
#define GTILES  24
#define NCH_W   24            /* K-chunks per 128-row W tile (768/32)  */
#define NCH_Z   48            /* K-chunks of z (1536/32)               */

#define NSTAGE      3
#define STAGE_BYTES 24576
#define SA_HI 0
#define SA_LO 8192
#define SB_HI 16384
#define SB_LO 20480
#define MBAR_OFF    73728
#define SMEM_BYTES  73984
#define OFF_SWV 36864
#define OFF_SWI 38912
#define NEG_BIG (-3.402823466e38f)

// ---- device scratch (static; no allocs). Weight/act tiles stored PRE-SWIZZLED:
// A-tile = 8KB: 128 rows x 64B (32 bf16), SW64 swizzle. B-tile = 4KB: 64 rows x 64B.
__device__ __align__(256) unsigned char g_Wouthi[(size_t)VTILES * NCH_W * 8192];
__device__ __align__(256) unsigned char g_Woutlo[(size_t)VTILES * NCH_W * 8192];
__device__ __align__(256) unsigned char g_Wghi[(size_t)GTILES * NCH_Z * 8192];
__device__ __align__(256) unsigned char g_Wglo[(size_t)GTILES * NCH_Z * 8192];
__device__ __align__(256) unsigned char g_hhi[NCH_W * 4096];
__device__ __align__(256) unsigned char g_hlo[NCH_W * 4096];
__device__ __align__(256) unsigned char g_zhi[NCH_Z * 4096];
__device__ __align__(256) unsigned char g_zlo[NCH_Z * 4096];
__device__ __align__(256) float g_h[NB * HID];
__device__ __align__(256) float g_c[NB * HID];
__device__ __align__(256) float g_gatesP[GPARTS * NGATE * NB];
__device__ __align__(256) unsigned long long g_amax[NB];

// ---- helpers ----
__device__ __forceinline__ uint32_t smem_u32(const void* p) {
    uint32_t a;
    asm("{ .reg .u64 t; cvta.to.shared.u64 t, %1; cvt.u32.u64 %0, t; }" : "=r"(a) : "l"(p));
    return a;
}
#define SWZ64(x) ((uint32_t)(x) ^ ((((uint32_t)(x)) >> 3) & 0x30u))

#define MBAR_INIT(a, c) asm volatile("mbarrier.init.shared.b64 [%0], %1;" :: "r"(a), "r"(c) : "memory")
#define MBAR_EXPECT(a, tx) asm volatile("mbarrier.arrive.expect_tx.shared.b64 _, [%0], %1;" :: "r"(a), "r"((uint32_t)(tx)) : "memory")
#define MBAR_WAIT(a, ph) do { \
    uint32_t _m = (a), _p = (ph), _d; \
    asm volatile("{ .reg .pred p; mbarrier.try_wait.parity.acquire.cta.shared::cta.b64 p, [%1], %2; selp.b32 %0,1,0,p; }" \
        : "=r"(_d) : "r"(_m), "r"(_p) : "memory"); \
    if (!_d) { \
        asm volatile("{ .reg .pred P1;\nWL_%=: mbarrier.try_wait.parity.acquire.cta.shared::cta.b64 P1, [%0], %1, 0x989680;\n@P1 bra.uni WD_%=;\nbra.uni WL_%=;\nWD_%=: }" \
            :: "r"(_m), "r"(_p) : "memory"); \
    } } while (0)

__device__ __forceinline__ uint64_t pol_keep() {
    uint64_t p;
    asm("createpolicy.fractional.L2::evict_last.b64 %0, 1.0;" : "=l"(p));
    return p;
}
__device__ __forceinline__ uint64_t pol_stream() {
    uint64_t p;
    asm("createpolicy.fractional.L2::evict_first.b64 %0, 1.0;" : "=l"(p));
    return p;
}
__device__ __forceinline__ void bulk_g2s(uint32_t sdst, const void* gsrc, uint32_t bytes,
                                         uint32_t mbar, uint64_t pol) {
    asm volatile("cp.async.bulk.shared::cluster.global.mbarrier::complete_tx::bytes.L2::cache_hint "
        "[%0], [%1], %2, [%3], %4;"
        :: "r"(sdst), "l"(gsrc), "r"(bytes), "r"(mbar), "l"(pol) : "memory");
}

__device__ __forceinline__ void ldsm4(uint32_t* r, uint32_t addr) {
    asm volatile("ldmatrix.sync.aligned.m8n8.x4.shared.b16 {%0,%1,%2,%3}, [%4];"
        : "=r"(r[0]), "=r"(r[1]), "=r"(r[2]), "=r"(r[3]) : "r"(addr));
}
__device__ __forceinline__ void mma16816(float* c, const uint32_t* a, const uint32_t* b) {
    asm volatile("mma.sync.aligned.m16n8k16.row.col.f32.bf16.bf16.f32 "
        "{%0,%1,%2,%3}, {%4,%5,%6,%7}, {%8,%9}, {%0,%1,%2,%3};"
        : "+f"(c[0]), "+f"(c[1]), "+f"(c[2]), "+f"(c[3])
        : "r"(a[0]), "r"(a[1]), "r"(a[2]), "r"(a[3]), "r"(b[0]), "r"(b[1]));
}

// monotonic float->uint key (orders like float compare)
__device__ __forceinline__ uint32_t fkey(float f) {
    uint32_t u = __float_as_uint(f);
    return (u & 0x80000000u) ? ~u : (u | 0x80000000u);
}

extern __shared__ __align__(1024) char dyn_smem[];

// issue bulk loads for chunk ch into stage ch%3 (leader thread only)
__device__ __forceinline__ void issue_chunk(uint32_t sb, uint32_t mb, int ch,
    const unsigned char* Ahi, const unsigned char* Alo,
    const unsigned char* Bhi, const unsigned char* Blo,
    uint64_t polAhi, uint64_t polAlo)
{
    uint32_t st = sb + (uint32_t)(ch % NSTAGE) * STAGE_BYTES;
    uint32_t m = mb + 8u * (ch % NSTAGE);
    MBAR_EXPECT(m, STAGE_BYTES);
    bulk_g2s(st + SA_HI, Ahi + (size_t)ch * 8192, 8192, m, polAhi);
    bulk_g2s(st + SA_LO, Alo + (size_t)ch * 8192, 8192, m, polAlo);
    bulk_g2s(st + SB_HI, Bhi + (size_t)ch * 4096, 4096, m, polAhi);
    bulk_g2s(st + SB_LO, Blo + (size_t)ch * 4096, 4096, m, polAhi);
}

// C[128,64] = sum_K (Ahi+Alo)[128,K] x (Bhi+Blo)[64,K]^T  (3 split GEMMs, lo*lo dropped)
// 8 warps, warp = 16 rows x 64 cols. Result in smem C[m][b], row stride 65 floats.
__device__ __forceinline__ void mma_mainloop(
    char* smem, uint32_t sb,
    const unsigned char* Ahi, const unsigned char* Alo,
    const unsigned char* Bhi, const unsigned char* Blo, int nchunks,
    uint64_t polAhi, uint64_t polAlo)
{
    const int tid = threadIdx.x;
    const int wid = tid >> 5, lane = tid & 31;
    const uint32_t mb = sb + MBAR_OFF;
    float acc[8][4];
#pragma unroll
    for (int nt = 0; nt < 8; nt++)
#pragma unroll
        for (int r = 0; r < 4; r++) acc[nt][r] = 0.f;

    if (tid == 0) {
#pragma unroll
        for (int s = 0; s < NSTAGE; s++) MBAR_INIT(mb + 8u * s, 1);
        asm volatile("fence.mbarrier_init.release.cluster;" ::: "memory");
    }
    __syncthreads();
    if (tid == 0) {
        issue_chunk(sb, mb, 0, Ahi, Alo, Bhi, Blo, polAhi, polAlo);
        issue_chunk(sb, mb, 1, Ahi, Alo, Bhi, Blo, polAhi, polAlo);
    }

    const int a_r = lane & 15;
    const int a_c = (lane >> 4) << 4;
    const int b_r = (lane & 7) + ((lane & 16) >> 1);
    const int b_c = (lane & 8) << 1;

    for (int ch = 0; ch < nchunks; ch++) {
        MBAR_WAIT(mb + 8u * (ch % NSTAGE), (ch / NSTAGE) & 1);
        uint32_t st = sb + (uint32_t)(ch % NSTAGE) * STAGE_BYTES;
#pragma unroll
        for (int ks = 0; ks < 2; ks++) {
            const int kb = ks * 32;
            uint32_t ah[4], al[4];
            {
                uint32_t so = SWZ64((wid * 16 + a_r) * 64 + kb + a_c);
                ldsm4(ah, st + SA_HI + so);
                ldsm4(al, st + SA_LO + so);
            }
            {
                uint32_t bh[4][4];
#pragma unroll
                for (int p = 0; p < 4; p++) {
                    uint32_t so = SWZ64((p * 16 + b_r) * 64 + kb + b_c);
                    ldsm4(bh[p], st + SB_HI + so);
                }
#pragma unroll
                for (int p = 0; p < 4; p++) {
                    mma16816(acc[2 * p],     ah, &bh[p][0]);
                    mma16816(acc[2 * p + 1], ah, &bh[p][2]);
                }
#pragma unroll
                for (int p = 0; p < 4; p++) {
                    mma16816(acc[2 * p],     al, &bh[p][0]);
                    mma16816(acc[2 * p + 1], al, &bh[p][2]);
                }
            }
            {
                uint32_t bl[4][4];
#pragma unroll
                for (int p = 0; p < 4; p++) {
                    uint32_t so = SWZ64((p * 16 + b_r) * 64 + kb + b_c);
                    ldsm4(bl[p], st + SB_LO + so);
                }
#pragma unroll
                for (int p = 0; p < 4; p++) {
                    mma16816(acc[2 * p],     ah, &bl[p][0]);
                    mma16816(acc[2 * p + 1], ah, &bl[p][2]);
                }
            }
        }
        __syncthreads();   // all warps done with stage (ch-1)%3 == (ch+2)%3
        if (tid == 0 && ch + 2 < nchunks)
            issue_chunk(sb, mb, ch + 2, Ahi, Alo, Bhi, Blo, polAhi, polAlo);
    }
    float* C = (float*)smem;
#pragma unroll
    for (int nt = 0; nt < 8; nt++)
#pragma unroll
        for (int r = 0; r < 4; r++) {
            int m = wid * 16 + (lane >> 2) + ((r & 2) ? 8 : 0);
            int n = nt * 8 + 2 * (lane & 3) + (r & 1);
            C[m * 65 + n] = acc[nt][r];
        }
    __syncthreads();
}

// ---- prep kernels (write PRE-SWIZZLED tile layouts) ----
__global__ void k_split_wout(const float* __restrict__ W) {
    size_t i = (size_t)blockIdx.x * 256 + threadIdx.x;
    if (i >= (size_t)VPAD * HID) return;
    int v = (int)(i / HID), k = (int)(i - (size_t)v * HID);
    float w = (v < VOCAB) ? W[(size_t)v * HID + k] : 0.f;
    __nv_bfloat16 hi = __float2bfloat16(w);
    __nv_bfloat16 lo = __float2bfloat16(w - __bfloat162float(hi));
    size_t off = ((size_t)(v >> 7) * NCH_W + (k >> 5)) * 8192
               + SWZ64((v & 127) * 64 + (k & 31) * 2);
    *(__nv_bfloat16*)(g_Wouthi + off) = hi;
    *(__nv_bfloat16*)(g_Woutlo + off) = lo;
}
__global__ void k_split_wg(const float* __restrict__ Wih, const float* __restrict__ Whh) {
    int i = blockIdx.x * 256 + threadIdx.x;
    if (i >= NGATE * KZ) return;
    int j = i / KZ, k = i - j * KZ;
    float w = (k < HID) ? Wih[j * HID + k] : Whh[j * HID + (k - HID)];
    __nv_bfloat16 hi = __float2bfloat16(w);
    __nv_bfloat16 lo = __float2bfloat16(w - __bfloat162float(hi));
    size_t off = ((size_t)(j >> 7) * NCH_Z + (k >> 5)) * 8192
               + SWZ64((j & 127) * 64 + (k & 31) * 2);
    *(__nv_bfloat16*)(g_Wghi + off) = hi;
    *(__nv_bfloat16*)(g_Wglo + off) = lo;
}
__global__ void k_init(const float* __restrict__ emb) {
    int i = blockIdx.x * 256 + threadIdx.x;
    if (i >= NB * KZ) return;
    int b = i / KZ, k = i - b * KZ;
    if (k < HID) { g_h[b * HID + k] = 0.f; g_c[b * HID + k] = 0.f; }
    float x = (k < HID) ? emb[HID + k] : 0.f;   // SOS token = row 1; z[,768:]=h0=0
    __nv_bfloat16 hi = __float2bfloat16(x);
    __nv_bfloat16 lo = __float2bfloat16(x - __bfloat162float(hi));
    uint32_t off = (uint32_t)(k >> 5) * 4096 + SWZ64(b * 64 + (k & 31) * 2);
    *(__nv_bfloat16*)(g_zhi + off) = hi;
    *(__nv_bfloat16*)(g_zlo + off) = lo;
}

// ---- gates GEMM: partial [3072,64] per K-part ----
__global__ void __launch_bounds__(256, 3) k_gates() {
    char* smem = dyn_smem;
    uint32_t sb = smem_u32(smem);
    uint64_t pk = pol_keep();
    int jt = blockIdx.x / GPARTS, part = blockIdx.x % GPARTS;
    const unsigned char* Ahi = g_Wghi + ((size_t)jt * NCH_Z + part * 8) * 8192;
    const unsigned char* Alo = g_Wglo + ((size_t)jt * NCH_Z + part * 8) * 8192;
    const unsigned char* Bhi = g_zhi + (size_t)part * 8 * 4096;
    const unsigned char* Blo = g_zlo + (size_t)part * 8 * 4096;
    mma_mainloop(smem, sb, Ahi, Alo, Bhi, Blo, 8, pk, pk);
    const float* C = (const float*)smem;
    int r = threadIdx.x >> 1, half = threadIdx.x & 1;
    int j = jt * 128 + r;
    float4* o = (float4*)(g_gatesP + ((size_t)part * NGATE + j) * 64 + half * 32);
    const float* row = C + r * 65 + half * 32;
#pragma unroll
    for (int b = 0; b < 32; b += 4)
        o[b >> 2] = make_float4(row[b], row[b + 1], row[b + 2], row[b + 3]);
}

// ---- LSTM elementwise (also resets the packed argmax accumulator) ----
__global__ void k_update(const float* __restrict__ b_ih, const float* __restrict__ b_hh) {
    int i = blockIdx.x * 256 + threadIdx.x;
    if (i >= NB * HID) return;
    if (i < NB) g_amax[i] = 0ull;
    int k = i >> 6, b = i & 63;
    float xi = b_ih[k] + b_hh[k];
    float xf = b_ih[HID + k] + b_hh[HID + k];
    float xg = b_ih[2 * HID + k] + b_hh[2 * HID + k];
    float xo = b_ih[3 * HID + k] + b_hh[3 * HID + k];
#pragma unroll
    for (int p = 0; p < GPARTS; p++) {
        size_t base = (size_t)p * NGATE;
        xi += g_gatesP[(base + k) * 64 + b];
        xf += g_gatesP[(base + HID + k) * 64 + b];
        xg += g_gatesP[(base + 2 * HID + k) * 64 + b];
        xo += g_gatesP[(base + 3 * HID + k) * 64 + b];
    }
    float ig = 1.f / (1.f + expf(-xi));
    float fg = 1.f / (1.f + expf(-xf));
    float gg = tanhf(xg);
    float og = 1.f / (1.f + expf(-xo));
    int hidx = b * HID + k;
    float c = fg * g_c[hidx] + ig * gg;
    float h = og * tanhf(c);
    g_c[hidx] = c; g_h[hidx] = h;
    __nv_bfloat16 hi = __float2bfloat16(h);
    __nv_bfloat16 lo = __float2bfloat16(h - __bfloat162float(hi));
    uint32_t off = (uint32_t)(k >> 5) * 4096 + SWZ64(b * 64 + (k & 31) * 2);
    *(__nv_bfloat16*)(g_hhi + off) = hi;
    *(__nv_bfloat16*)(g_hlo + off) = lo;
    uint32_t zoff = off + (uint32_t)NCH_W * 4096;   // z chunks 24..47
    *(__nv_bfloat16*)(g_zhi + zoff) = hi;
    *(__nv_bfloat16*)(g_zlo + zoff) = lo;
}

// ---- logits GEMM + bias + store + packed atomic argmax ----
__global__ void __launch_bounds__(256, 3) k_logits(const float* __restrict__ b_out,
                                                   float* __restrict__ out, int t) {
    char* smem = dyn_smem;
    uint32_t sb = smem_u32(smem);
    uint64_t pk = pol_keep(), ps = pol_stream();
    const unsigned char* Ahi = g_Wouthi + (size_t)blockIdx.x * NCH_W * 8192;
    const unsigned char* Alo = g_Woutlo + (size_t)blockIdx.x * NCH_W * 8192;
    mma_mainloop(smem, sb, Ahi, Alo, g_hhi, g_hlo, NCH_W, pk, ps);
    const float* C = (const float*)smem;

    int wid = threadIdx.x >> 5, lane = threadIdx.x & 31;
    int vloc = threadIdx.x & 127;
    int grp = threadIdx.x >> 7;           // b-half: 0 -> b 0..31, 1 -> b 32..63
    int v = blockIdx.x * 128 + vloc;
    bool valid = (v < VOCAB);
    float bias = valid ? b_out[v] : NEG_BIG;
    float* op = out + (size_t)t * VOCAB + v;
    const float* row = C + vloc * 65 + grp * 32;
    float* swv = (float*)(smem + OFF_SWV);
    int*   swi = (int*)(smem + OFF_SWI);

#pragma unroll 8
    for (int b = 0; b < 32; b++) {
        int bb = grp * 32 + b;
        float val = row[b] + bias;
        if (valid) op[(size_t)bb * ((size_t)MAXLEN * VOCAB)] = val;
        float rm = val; int ri = v;
#pragma unroll
        for (int off = 16; off; off >>= 1) {
            float ov = __shfl_down_sync(0xffffffffu, rm, off);
            int oi = __shfl_down_sync(0xffffffffu, ri, off);
            if (ov > rm || (ov == rm && oi < ri)) { rm = ov; ri = oi; }
        }
        if (lane == 0) { swv[wid * 32 + b] = rm; swi[wid * 32 + b] = ri; }
    }
    __syncthreads();
    if (threadIdx.x < 64) {
        int b = threadIdx.x;
        int g0 = (b >> 5) * 4;
        int e = b & 31;
        float bm = swv[g0 * 32 + e]; int bi = swi[g0 * 32 + e];
#pragma unroll
        for (int w2 = 1; w2 < 4; w2++) {
            float ov = swv[(g0 + w2) * 32 + e]; int oi = swi[(g0 + w2) * 32 + e];
            if (ov > bm || (ov == bm && oi < bi)) { bm = ov; bi = oi; }
        }
        unsigned long long key = ((unsigned long long)fkey(bm) << 32)
                               | (unsigned long long)(uint32_t)(0x7fffffff - bi);
        atomicMax(&g_amax[b], key);
    }
}

// ---- decode argmax + build z first half ----
__global__ void k_argmax_z(const float* __restrict__ emb) {
    int b = blockIdx.x, tid = threadIdx.x;  // 128 threads
    int tok = 0x7fffffff - (int)(uint32_t)(g_amax[b] & 0xffffffffull);
    for (int k = tid; k < HID; k += 128) {
        float x = emb[(size_t)tok * HID + k];
        __nv_bfloat16 hi = __float2bfloat16(x);
        __nv_bfloat16 lo = __float2bfloat16(x - __bfloat162float(hi));
        uint32_t off = (uint32_t)(k >> 5) * 4096 + SWZ64(b * 64 + (k & 31) * 2);
        *(__nv_bfloat16*)(g_zhi + off) = hi;
        *(__nv_bfloat16*)(g_zlo + off) = lo;
    }
}

// ---- final h,c copy into output tail ----
__global__ void k_finalhc(float* __restrict__ out) {
    int i = blockIdx.x * 256 + threadIdx.x;
    if (i >= NB * HID) return;
    size_t base = (size_t)NB * MAXLEN * VOCAB;
    out[base + i] = g_h[i];
    out[base + (size_t)NB * HID + i] = g_c[i];
}

extern "C" void kernel_launch(void* const* d_in, const int* in_sizes, int n_in,
                              void* d_out, int out_size) {
    const float* emb   = (const float*)d_in[1];
    const float* W_ih  = (const float*)d_in[2];
    const float* W_hh  = (const float*)d_in[3];
    const float* b_ih  = (const float*)d_in[4];
    const float* b_hh  = (const float*)d_in[5];
    const float* W_out = (const float*)d_in[6];
    const float* b_out = (const float*)d_in[7];
    float* out = (float*)d_out;

    cudaFuncSetAttribute(k_gates,  cudaFuncAttributeMaxDynamicSharedMemorySize, SMEM_BYTES);
    cudaFuncSetAttribute(k_logits, cudaFuncAttributeMaxDynamicSharedMemorySize, SMEM_BYTES);

    k_split_wout<<<(int)(((size_t)VPAD * HID + 255) / 256), 256>>>(W_out);
    k_split_wg<<<(NGATE * KZ + 255) / 256, 256>>>(W_ih, W_hh);
    k_init<<<(NB * KZ + 255) / 256, 256>>>(emb);

    for (int t = 0; t < MAXLEN; t++) {
        k_gates<<<GTILES * GPARTS, 256, SMEM_BYTES>>>();
        k_update<<<(NB * HID + 255) / 256, 256>>>(b_ih, b_hh);
        k_logits<<<VTILES, 256, SMEM_BYTES>>>(b_out, out, t);
        k_argmax_z<<<NB, 128>>>(emb);
    }
    k_finalhc<<<(NB * HID + 255) / 256, 256>>>(out);
}